// round 13
// baseline (speedup 1.0000x reference)
#include <cuda_runtime.h>
#include <cuda_bf16.h>
#include <cstdint>

// Problem constants (fixed-shape problem)
#define HIDDEN   128
#define N_NODES  1000000
#define N_GRAPHS 4096

#define ROWS_PER_WARP 64
#define N_WARPSPANS   (N_NODES / ROWS_PER_WARP)   // 15625
#define POOL_THREADS  256
#define POOL_BLOCKS   ((N_WARPSPANS + (POOL_THREADS/32) - 1) / (POOL_THREADS/32))

// ------------------------------------------------------------------
// Unified scratch: ONE cudaMemsetAsync(0) re-establishes ALL state
// (including the completion counters) every replay. sums=0, h=0,
// counts=0, done=0, and maxs=0 == enc(-inf) via zero-based encoding.
// ------------------------------------------------------------------
#define N_GROUPS 256
struct Scratch {
    float    sums[N_GRAPHS * HIDDEN];
    unsigned maxs[N_GRAPHS * HIDDEN];
    float    h[N_GRAPHS * HIDDEN];
    int      counts[N_GRAPHS];
    int      done[N_GROUPS];
};
__device__ __align__(16) Scratch g_S;

// ---- zero-based ordered-uint float encoding (enc(-inf) == 0) ----
#define ORD_BIAS 0x007FFFFFu
__device__ __forceinline__ unsigned encf(float f) {
    unsigned u = __float_as_uint(f);
    unsigned o = (u & 0x80000000u) ? ~u : (u | 0x80000000u);
    return o - ORD_BIAS;
}
__device__ __forceinline__ float decf(unsigned s) {
    unsigned u = s + ORD_BIAS;
    return __uint_as_float((u & 0x80000000u) ? (u ^ 0x80000000u) : ~u);
}

// ------------------------------------------------------------------
// Kernel 1: pooling — exact R9/R12 configuration (80 regs, ~84us,
// 6.2TB/s measured). Plain launch. DO NOT PERTURB.
// ------------------------------------------------------------------
__device__ __forceinline__ void flush_seg(int g, float4 a, float4 m, int n, int lane) {
    if ((unsigned)g >= N_GRAPHS) return;
    float*    sp = &g_S.sums[g * HIDDEN + 4 * lane];
    unsigned* mp = &g_S.maxs[g * HIDDEN + 4 * lane];
    atomicAdd(sp + 0, a.x);
    atomicAdd(sp + 1, a.y);
    atomicAdd(sp + 2, a.z);
    atomicAdd(sp + 3, a.w);
    atomicMax(mp + 0, encf(m.x));
    atomicMax(mp + 1, encf(m.y));
    atomicMax(mp + 2, encf(m.z));
    atomicMax(mp + 3, encf(m.w));
    if (lane == 0) atomicAdd(&g_S.counts[g], n);
}

template <typename IT>
__device__ __forceinline__ void pool_span(const float4* __restrict__ x4,
                                          const IT* __restrict__ batch,
                                          int row0, int lane) {
    const float NEG_INF = -__int_as_float(0x7F800000);
    float4 acc = make_float4(0.f, 0.f, 0.f, 0.f);
    float4 mx  = make_float4(NEG_INF, NEG_INF, NEG_INF, NEG_INF);
    int cur = -1, seglen = 0;

    for (int mb = 0; mb < ROWS_PER_WARP / 8; mb++) {
        int base = row0 + mb * 8;
        int    bb[8];
        float4 vv[8];
        #pragma unroll
        for (int i = 0; i < 8; i++) {
            bb[i] = (int)batch[base + i];
            vv[i] = __ldcs(&x4[(size_t)(base + i) * (HIDDEN / 4) + lane]);
        }
        #pragma unroll
        for (int i = 0; i < 8; i++) {
            int g = bb[i];
            if (g != cur) {
                if (cur >= 0) flush_seg(cur, acc, mx, seglen, lane);
                cur = g;
                acc = make_float4(0.f, 0.f, 0.f, 0.f);
                mx  = make_float4(NEG_INF, NEG_INF, NEG_INF, NEG_INF);
                seglen = 0;
            }
            acc.x += vv[i].x; acc.y += vv[i].y; acc.z += vv[i].z; acc.w += vv[i].w;
            mx.x = fmaxf(mx.x, vv[i].x); mx.y = fmaxf(mx.y, vv[i].y);
            mx.z = fmaxf(mx.z, vv[i].z); mx.w = fmaxf(mx.w, vv[i].w);
            seglen++;
        }
    }
    flush_seg(cur, acc, mx, seglen, lane);
}

__global__ __launch_bounds__(POOL_THREADS)
void pool_kernel(const float4* __restrict__ x4, const void* __restrict__ batch) {
    int wg   = (blockIdx.x * blockDim.x + threadIdx.x) >> 5;
    int lane = threadIdx.x & 31;
    if (wg >= N_WARPSPANS) return;
    int row0 = wg * ROWS_PER_WARP;

    // inline dtype probe: sorted ids < 4096 => int64 high words all zero
    const int2* b2 = (const int2*)batch;
    int nz = 0;
    #pragma unroll
    for (int k = 1; k <= 8; k++) {
        nz |= b2[N_NODES / 2 - k].y;
        nz |= b2[N_NODES / 4 + k].y;
    }
    if (nz == 0) pool_span<long long>(x4, (const long long*)batch, row0, lane);
    else         pool_span<int>(x4, (const int*)batch, row0, lane);
}

// ------------------------------------------------------------------
// Kernel 2: fused split-K GEMM + completion-counter finisher.
// Grid = 12 k-tiles(32) x 256 groups(16 graphs) = 3072 blocks x 128 thr.
// REDG partials into memset-zeroed g_S.h. The 12th block to finish a
// group applies bias + LayerNorm + exact GELU and writes out.
// Counters are memset-zeroed EVERY replay (no cross-replay state).
// ------------------------------------------------------------------
#define S1_KT   32
#define S1_GPB  16
#define S1_GPW  4
#define N_KT    12

__device__ __forceinline__ void ffma2(unsigned long long& acc,
                                      unsigned long long w2,
                                      unsigned long long p2) {
    asm("fma.rn.f32x2 %0, %1, %2, %0;" : "+l"(acc) : "l"(w2), "l"(p2));
}
__device__ __forceinline__ unsigned long long pack2(float p) {
    unsigned long long r;
    asm("mov.b64 %0, {%1, %1};" : "=l"(r) : "r"(__float_as_uint(p)));
    return r;
}

__global__ __launch_bounds__(128, 8)
void gemm_fused(const float* __restrict__ W, const float* __restrict__ bias,
                const float* __restrict__ gamma, const float* __restrict__ beta,
                float* __restrict__ out) {
    __shared__ float Ws[S1_KT * HIDDEN];      // 16 KB
    __shared__ float Ps[S1_GPB][S1_KT];       // 2 KB
    __shared__ int   s_last;

    int kt   = blockIdx.x / N_GROUPS;          // 0..11
    int grp  = blockIdx.x % N_GROUPS;          // 0..255
    int g0   = grp * S1_GPB;
    int tid  = threadIdx.x;                    // 128
    int warp = tid >> 5, lane = tid & 31;
    int glb  = warp * S1_GPW;

    // ---- PDL prologue: W tile (independent of pool) ----
    const float4* Wg = (const float4*)(W + kt * S1_KT * HIDDEN);
    #pragma unroll
    for (int i = 0; i < 8; i++) ((float4*)Ws)[tid + i * 128] = Wg[tid + i * 128];

    cudaGridDependencySynchronize();

    // Ps: warp's 4 graphs x 32 pooled values. tiles 0-3 mean, 4-7 max, 8-11 sum
    int sec = kt >> 2;
    int lc  = (kt & 3) * 32 + lane;            // col within section, 0..127
    #pragma unroll
    for (int g = 0; g < S1_GPW; g++) {
        int gg  = g0 + glb + g;
        int cnt = g_S.counts[gg];
        float v;
        if (sec == 0)      v = g_S.sums[gg * HIDDEN + lc] * (1.0f / fmaxf((float)cnt, 1.0f));
        else if (sec == 1) v = (cnt > 0) ? decf(g_S.maxs[gg * HIDDEN + lc]) : 0.f;
        else               v = g_S.sums[gg * HIDDEN + lc];
        Ps[glb + g][lane] = v;
    }
    __syncthreads();

    unsigned long long acc[S1_GPW][2];
    #pragma unroll
    for (int g = 0; g < S1_GPW; g++) { acc[g][0] = 0ull; acc[g][1] = 0ull; }

    #pragma unroll
    for (int k4 = 0; k4 < S1_KT / 4; k4++) {
        float4 pv[S1_GPW];
        #pragma unroll
        for (int g = 0; g < S1_GPW; g++)
            pv[g] = ((const float4*)Ps[glb + g])[k4];           // broadcast LDS.128
        #pragma unroll
        for (int kk = 0; kk < 4; kk++) {
            ulonglong2 w2 = ((const ulonglong2*)(Ws + (k4 * 4 + kk) * HIDDEN))[lane];
            #pragma unroll
            for (int g = 0; g < S1_GPW; g++) {
                float p = (kk == 0) ? pv[g].x : (kk == 1) ? pv[g].y
                        : (kk == 2) ? pv[g].z : pv[g].w;
                unsigned long long p2 = pack2(p);
                ffma2(acc[g][0], w2.x, p2);
                ffma2(acc[g][1], w2.y, p2);
            }
        }
    }

    // REDG partial accumulation into memset-zeroed g_S.h
    #pragma unroll
    for (int g = 0; g < S1_GPW; g++) {
        int gg = g0 + glb + g;
        float* hp = &g_S.h[gg * HIDDEN + 4 * lane];
        unsigned lo, hi;
        asm("mov.b64 {%0, %1}, %2;" : "=r"(lo), "=r"(hi) : "l"(acc[g][0]));
        atomicAdd(hp + 0, __uint_as_float(lo));
        atomicAdd(hp + 1, __uint_as_float(hi));
        asm("mov.b64 {%0, %1}, %2;" : "=r"(lo), "=r"(hi) : "l"(acc[g][1]));
        atomicAdd(hp + 2, __uint_as_float(lo));
        atomicAdd(hp + 3, __uint_as_float(hi));
    }

    // ---- completion protocol (threadFenceReduction pattern) ----
    __threadfence();
    __syncthreads();
    if (tid == 0) {
        int old = atomicAdd(&g_S.done[grp], 1);
        s_last = (old == N_KT - 1);
    }
    __syncthreads();
    if (!s_last) return;
    __threadfence();   // acquire: all groups' REDs visible via L2

    // ---- finisher: bias + LayerNorm + exact GELU for 16 graphs ----
    float4 b4 = ((const float4*)bias)[lane];
    float4 gm = ((const float4*)gamma)[lane];
    float4 bt = ((const float4*)beta)[lane];

    #pragma unroll
    for (int g = 0; g < S1_GPW; g++) {
        int gg = g0 + glb + g;
        float4 p = __ldcg(&((const float4*)g_S.h)[(size_t)gg * (HIDDEN / 4) + lane]);
        float h[4];
        h[0] = p.x + b4.x; h[1] = p.y + b4.y; h[2] = p.z + b4.z; h[3] = p.w + b4.w;

        float s = h[0] + h[1] + h[2] + h[3];
        #pragma unroll
        for (int o = 16; o; o >>= 1) s += __shfl_xor_sync(0xFFFFFFFFu, s, o);
        float mu = s * (1.0f / 128.0f);

        float d0 = h[0]-mu, d1 = h[1]-mu, d2 = h[2]-mu, d3 = h[3]-mu;
        float v = d0*d0 + d1*d1 + d2*d2 + d3*d3;
        #pragma unroll
        for (int o = 16; o; o >>= 1) v += __shfl_xor_sync(0xFFFFFFFFu, v, o);
        float rstd = rsqrtf(v * (1.0f / 128.0f) + 1e-5f);

        float gmv[4] = {gm.x, gm.y, gm.z, gm.w};
        float btv[4] = {bt.x, bt.y, bt.z, bt.w};
        float4 o4;
        float* ov = (float*)&o4;
        #pragma unroll
        for (int k = 0; k < 4; k++) {
            float t = (h[k] - mu) * rstd * gmv[k] + btv[k];
            ov[k] = 0.5f * t * (1.0f + erff(t * 0.70710678118654752f));
        }
        ((float4*)out)[(size_t)gg * (HIDDEN / 4) + lane] = o4;
    }
}

// ------------------------------------------------------------------
extern "C" void kernel_launch(void* const* d_in, const int* in_sizes, int n_in,
                              void* d_out, int out_size) {
    const float* x     = nullptr;
    const void*  batch = nullptr;
    const float* W     = nullptr;
    const float* b     = nullptr;
    const float* gamma = nullptr;
    const float* beta  = nullptr;

    for (int i = 0; i < n_in; i++) {
        int s = in_sizes[i];
        if (s == N_NODES * HIDDEN)         x = (const float*)d_in[i];
        else if (s == N_NODES)             batch = d_in[i];
        else if (s == 3 * HIDDEN * HIDDEN) W = (const float*)d_in[i];
        else if (s == HIDDEN) {
            if (!b) b = (const float*)d_in[i];
            else if (!gamma) gamma = (const float*)d_in[i];
            else if (!beta)  beta = (const float*)d_in[i];
        }
    }

    // single memset node zeroes ALL scratch INCLUDING done counters,
    // every replay — no state survives a replay.
    void* scratch_ptr = nullptr;
    cudaGetSymbolAddress(&scratch_ptr, g_S);
    cudaMemsetAsync(scratch_ptr, 0, sizeof(Scratch), 0);

    // pool: plain launch (fastest measured pool — do not perturb)
    pool_kernel<<<POOL_BLOCKS, POOL_THREADS>>>((const float4*)x, batch);

    // fused gemm+finish with PDL (W-tile prologue overlaps pool drain)
    cudaLaunchAttribute pdl[1];
    pdl[0].id = cudaLaunchAttributeProgrammaticStreamSerialization;
    pdl[0].val.programmaticStreamSerializationAllowed = 1;

    {
        cudaLaunchConfig_t cfg = {};
        cfg.gridDim  = dim3(N_KT * N_GROUPS);
        cfg.blockDim = dim3(128);
        cfg.stream   = 0;
        cfg.attrs    = pdl;
        cfg.numAttrs = 1;
        cudaLaunchKernelEx(&cfg, gemm_fused, W, b, gamma, beta, (float*)d_out);
    }
}

// round 14
// speedup vs baseline: 1.0648x; 1.0648x over previous
#include <cuda_runtime.h>
#include <cuda_bf16.h>
#include <cstdint>

// Problem constants (fixed-shape problem)
#define HIDDEN   128
#define N_NODES  1000000
#define N_GRAPHS 4096

#define ROWS_PER_WARP 64
#define N_WARPSPANS   (N_NODES / ROWS_PER_WARP)   // 15625
#define POOL_THREADS  256
#define POOL_BLOCKS   ((N_WARPSPANS + (POOL_THREADS/32) - 1) / (POOL_THREADS/32))

// ------------------------------------------------------------------
// Unified scratch: ONE cudaMemsetAsync(0) initializes everything.
// sums=0, h=0, counts=0, and maxs=0 == enc(-inf) via zero-based encoding.
// ------------------------------------------------------------------
struct Scratch {
    float    sums[N_GRAPHS * HIDDEN];
    unsigned maxs[N_GRAPHS * HIDDEN];
    float    h[N_GRAPHS * HIDDEN];
    int      counts[N_GRAPHS];
};
__device__ __align__(16) Scratch g_S;

// ---- zero-based ordered-uint float encoding (enc(-inf) == 0) ----
#define ORD_BIAS 0x007FFFFFu
__device__ __forceinline__ unsigned encf(float f) {
    unsigned u = __float_as_uint(f);
    unsigned o = (u & 0x80000000u) ? ~u : (u | 0x80000000u);
    return o - ORD_BIAS;
}
__device__ __forceinline__ float decf(unsigned s) {
    unsigned u = s + ORD_BIAS;
    return __uint_as_float((u & 0x80000000u) ? (u ^ 0x80000000u) : ~u);
}

// ------------------------------------------------------------------
// Kernel 1: pooling — exact R9/R12 configuration (80 regs, ~84-85us,
// 6.2TB/s measured). Plain launch. DO NOT PERTURB.
// ------------------------------------------------------------------
__device__ __forceinline__ void flush_seg(int g, float4 a, float4 m, int n, int lane) {
    if ((unsigned)g >= N_GRAPHS) return;
    float*    sp = &g_S.sums[g * HIDDEN + 4 * lane];
    unsigned* mp = &g_S.maxs[g * HIDDEN + 4 * lane];
    atomicAdd(sp + 0, a.x);
    atomicAdd(sp + 1, a.y);
    atomicAdd(sp + 2, a.z);
    atomicAdd(sp + 3, a.w);
    atomicMax(mp + 0, encf(m.x));
    atomicMax(mp + 1, encf(m.y));
    atomicMax(mp + 2, encf(m.z));
    atomicMax(mp + 3, encf(m.w));
    if (lane == 0) atomicAdd(&g_S.counts[g], n);
}

template <typename IT>
__device__ __forceinline__ void pool_span(const float4* __restrict__ x4,
                                          const IT* __restrict__ batch,
                                          int row0, int lane) {
    const float NEG_INF = -__int_as_float(0x7F800000);
    float4 acc = make_float4(0.f, 0.f, 0.f, 0.f);
    float4 mx  = make_float4(NEG_INF, NEG_INF, NEG_INF, NEG_INF);
    int cur = -1, seglen = 0;

    for (int mb = 0; mb < ROWS_PER_WARP / 8; mb++) {
        int base = row0 + mb * 8;
        int    bb[8];
        float4 vv[8];
        #pragma unroll
        for (int i = 0; i < 8; i++) {
            bb[i] = (int)batch[base + i];
            vv[i] = __ldcs(&x4[(size_t)(base + i) * (HIDDEN / 4) + lane]);
        }
        #pragma unroll
        for (int i = 0; i < 8; i++) {
            int g = bb[i];
            if (g != cur) {
                if (cur >= 0) flush_seg(cur, acc, mx, seglen, lane);
                cur = g;
                acc = make_float4(0.f, 0.f, 0.f, 0.f);
                mx  = make_float4(NEG_INF, NEG_INF, NEG_INF, NEG_INF);
                seglen = 0;
            }
            acc.x += vv[i].x; acc.y += vv[i].y; acc.z += vv[i].z; acc.w += vv[i].w;
            mx.x = fmaxf(mx.x, vv[i].x); mx.y = fmaxf(mx.y, vv[i].y);
            mx.z = fmaxf(mx.z, vv[i].z); mx.w = fmaxf(mx.w, vv[i].w);
            seglen++;
        }
    }
    flush_seg(cur, acc, mx, seglen, lane);
}

__global__ __launch_bounds__(POOL_THREADS)
void pool_kernel(const float4* __restrict__ x4, const void* __restrict__ batch) {
    int wg   = (blockIdx.x * blockDim.x + threadIdx.x) >> 5;
    int lane = threadIdx.x & 31;
    if (wg >= N_WARPSPANS) return;
    int row0 = wg * ROWS_PER_WARP;

    // inline dtype probe: sorted ids < 4096 => int64 high words all zero
    const int2* b2 = (const int2*)batch;
    int nz = 0;
    #pragma unroll
    for (int k = 1; k <= 8; k++) {
        nz |= b2[N_NODES / 2 - k].y;
        nz |= b2[N_NODES / 4 + k].y;
    }
    if (nz == 0) pool_span<long long>(x4, (const long long*)batch, row0, lane);
    else         pool_span<int>(x4, (const int*)batch, row0, lane);
}

// ------------------------------------------------------------------
// Kernel 2: split-K GEMM (R8/R12 structure) + PDL.
// launch_bounds(128,6): 24 warps/SM but ~84-reg budget — no spill risk
// in the FFMA2 hot loop (R13 showed the 64-reg cap spills when code
// grows; keep headroom).
// ------------------------------------------------------------------
#define S1_KT   32
#define S1_GPB  16
#define S1_GPW  4
#define N_KT    12

__device__ __forceinline__ void ffma2(unsigned long long& acc,
                                      unsigned long long w2,
                                      unsigned long long p2) {
    asm("fma.rn.f32x2 %0, %1, %2, %0;" : "+l"(acc) : "l"(w2), "l"(p2));
}
__device__ __forceinline__ unsigned long long pack2(float p) {
    unsigned long long r;
    asm("mov.b64 %0, {%1, %1};" : "=l"(r) : "r"(__float_as_uint(p)));
    return r;
}

__global__ __launch_bounds__(128, 6)
void gemm_stage1(const float* __restrict__ W) {
    __shared__ float Ws[S1_KT * HIDDEN];      // 16 KB
    __shared__ float Ps[S1_GPB][S1_KT];       // 2 KB

    int kt   = blockIdx.x / 256;               // 0..11
    int grp  = blockIdx.x % 256;               // 0..255
    int g0   = grp * S1_GPB;
    int tid  = threadIdx.x;                    // 128
    int warp = tid >> 5, lane = tid & 31;
    int glb  = warp * S1_GPW;

    // ---- PDL prologue: W tile (independent of pool) ----
    const float4* Wg = (const float4*)(W + kt * S1_KT * HIDDEN);
    #pragma unroll
    for (int i = 0; i < 8; i++) ((float4*)Ws)[tid + i * 128] = Wg[tid + i * 128];

    cudaGridDependencySynchronize();

    // Ps: warp's 4 graphs x 32 pooled values. tiles 0-3 mean, 4-7 max, 8-11 sum
    int sec = kt >> 2;
    int lc  = (kt & 3) * 32 + lane;            // col within section, 0..127
    #pragma unroll
    for (int g = 0; g < S1_GPW; g++) {
        int gg  = g0 + glb + g;
        int cnt = g_S.counts[gg];
        float v;
        if (sec == 0)      v = g_S.sums[gg * HIDDEN + lc] * (1.0f / fmaxf((float)cnt, 1.0f));
        else if (sec == 1) v = (cnt > 0) ? decf(g_S.maxs[gg * HIDDEN + lc]) : 0.f;
        else               v = g_S.sums[gg * HIDDEN + lc];
        Ps[glb + g][lane] = v;
    }
    __syncthreads();

    unsigned long long acc[S1_GPW][2];
    #pragma unroll
    for (int g = 0; g < S1_GPW; g++) { acc[g][0] = 0ull; acc[g][1] = 0ull; }

    #pragma unroll
    for (int k4 = 0; k4 < S1_KT / 4; k4++) {
        float4 pv[S1_GPW];
        #pragma unroll
        for (int g = 0; g < S1_GPW; g++)
            pv[g] = ((const float4*)Ps[glb + g])[k4];           // broadcast LDS.128
        #pragma unroll
        for (int kk = 0; kk < 4; kk++) {
            ulonglong2 w2 = ((const ulonglong2*)(Ws + (k4 * 4 + kk) * HIDDEN))[lane];
            #pragma unroll
            for (int g = 0; g < S1_GPW; g++) {
                float p = (kk == 0) ? pv[g].x : (kk == 1) ? pv[g].y
                        : (kk == 2) ? pv[g].z : pv[g].w;
                unsigned long long p2 = pack2(p);
                ffma2(acc[g][0], w2.x, p2);
                ffma2(acc[g][1], w2.y, p2);
            }
        }
    }

    // REDG partial accumulation into memset-zeroed g_S.h
    #pragma unroll
    for (int g = 0; g < S1_GPW; g++) {
        int gg = g0 + glb + g;
        float* hp = &g_S.h[gg * HIDDEN + 4 * lane];
        unsigned lo, hi;
        asm("mov.b64 {%0, %1}, %2;" : "=r"(lo), "=r"(hi) : "l"(acc[g][0]));
        atomicAdd(hp + 0, __uint_as_float(lo));
        atomicAdd(hp + 1, __uint_as_float(hi));
        asm("mov.b64 {%0, %1}, %2;" : "=r"(lo), "=r"(hi) : "l"(acc[g][1]));
        atomicAdd(hp + 2, __uint_as_float(lo));
        atomicAdd(hp + 3, __uint_as_float(hi));
    }
}

// ------------------------------------------------------------------
// Kernel 3: finisher + PDL — bias + LayerNorm + exact GELU.
// 256 blocks x 256 threads; warp = 2 graphs; lane = 4 cols.
// ------------------------------------------------------------------
__global__ __launch_bounds__(256)
void finish_kernel(const float* __restrict__ bias, const float* __restrict__ gamma,
                   const float* __restrict__ beta, float* __restrict__ out) {
    int tid  = threadIdx.x;
    int warp = tid >> 5, lane = tid & 31;

    // ---- PDL prologue: params (independent of gemm) ----
    float4 b4 = ((const float4*)bias)[lane];
    float4 gm = ((const float4*)gamma)[lane];
    float4 bt = ((const float4*)beta)[lane];

    cudaGridDependencySynchronize();

    #pragma unroll
    for (int gi = 0; gi < 2; gi++) {
        int g = (blockIdx.x * 8 + warp) * 2 + gi;

        float4 p = ((const float4*)g_S.h)[(size_t)g * (HIDDEN / 4) + lane];
        float h[4];
        h[0] = p.x + b4.x; h[1] = p.y + b4.y; h[2] = p.z + b4.z; h[3] = p.w + b4.w;

        float s = h[0] + h[1] + h[2] + h[3];
        #pragma unroll
        for (int o = 16; o; o >>= 1) s += __shfl_xor_sync(0xFFFFFFFFu, s, o);
        float mu = s * (1.0f / 128.0f);

        float d0 = h[0]-mu, d1 = h[1]-mu, d2 = h[2]-mu, d3 = h[3]-mu;
        float v = d0*d0 + d1*d1 + d2*d2 + d3*d3;
        #pragma unroll
        for (int o = 16; o; o >>= 1) v += __shfl_xor_sync(0xFFFFFFFFu, v, o);
        float rstd = rsqrtf(v * (1.0f / 128.0f) + 1e-5f);

        float gmv[4] = {gm.x, gm.y, gm.z, gm.w};
        float btv[4] = {bt.x, bt.y, bt.z, bt.w};
        float4 o4;
        float* ov = (float*)&o4;
        #pragma unroll
        for (int k = 0; k < 4; k++) {
            float t = (h[k] - mu) * rstd * gmv[k] + btv[k];
            ov[k] = 0.5f * t * (1.0f + erff(t * 0.70710678118654752f));
        }
        ((float4*)out)[(size_t)g * (HIDDEN / 4) + lane] = o4;
    }
}

// ------------------------------------------------------------------
extern "C" void kernel_launch(void* const* d_in, const int* in_sizes, int n_in,
                              void* d_out, int out_size) {
    const float* x     = nullptr;
    const void*  batch = nullptr;
    const float* W     = nullptr;
    const float* b     = nullptr;
    const float* gamma = nullptr;
    const float* beta  = nullptr;

    for (int i = 0; i < n_in; i++) {
        int s = in_sizes[i];
        if (s == N_NODES * HIDDEN)         x = (const float*)d_in[i];
        else if (s == N_NODES)             batch = d_in[i];
        else if (s == 3 * HIDDEN * HIDDEN) W = (const float*)d_in[i];
        else if (s == HIDDEN) {
            if (!b) b = (const float*)d_in[i];
            else if (!gamma) gamma = (const float*)d_in[i];
            else if (!beta)  beta = (const float*)d_in[i];
        }
    }

    // single memset node replaces the init kernel (zero-based max encoding)
    void* scratch_ptr = nullptr;
    cudaGetSymbolAddress(&scratch_ptr, g_S);
    cudaMemsetAsync(scratch_ptr, 0, sizeof(Scratch), 0);

    // pool: plain launch (fastest measured pool — do not perturb)
    pool_kernel<<<POOL_BLOCKS, POOL_THREADS>>>((const float4*)x, batch);

    // PDL on the two tail kernels (prologue overlap, measured -4us)
    cudaLaunchAttribute pdl[1];
    pdl[0].id = cudaLaunchAttributeProgrammaticStreamSerialization;
    pdl[0].val.programmaticStreamSerializationAllowed = 1;

    {
        cudaLaunchConfig_t cfg = {};
        cfg.gridDim  = dim3(N_KT * 256);
        cfg.blockDim = dim3(128);
        cfg.stream   = 0;
        cfg.attrs    = pdl;
        cfg.numAttrs = 1;
        cudaLaunchKernelEx(&cfg, gemm_stage1, W);
    }
    {
        cudaLaunchConfig_t cfg = {};
        cfg.gridDim  = dim3(256);
        cfg.blockDim = dim3(256);
        cfg.stream   = 0;
        cfg.attrs    = pdl;
        cfg.numAttrs = 1;
        cudaLaunchKernelEx(&cfg, finish_kernel, b, gamma, beta, (float*)d_out);
    }
}

// round 15
// speedup vs baseline: 1.0947x; 1.0281x over previous
#include <cuda_runtime.h>
#include <cuda_bf16.h>
#include <cstdint>

// Problem constants (fixed-shape problem)
#define HIDDEN   128
#define N_NODES  1000000
#define N_GRAPHS 4096

#define ROWS_PER_WARP 64
#define N_WARPSPANS   (N_NODES / ROWS_PER_WARP)   // 15625
#define POOL_THREADS  256
#define POOL_BLOCKS   ((N_WARPSPANS + (POOL_THREADS/32) - 1) / (POOL_THREADS/32))

// ------------------------------------------------------------------
// Unified scratch: ONE cudaMemsetAsync(0) initializes everything.
// sums=0, h=0, counts=0, and maxs=0 == enc(-inf) via zero-based encoding.
// ------------------------------------------------------------------
struct Scratch {
    float    sums[N_GRAPHS * HIDDEN];
    unsigned maxs[N_GRAPHS * HIDDEN];
    float    h[N_GRAPHS * HIDDEN];
    int      counts[N_GRAPHS];
};
__device__ __align__(16) Scratch g_S;

// ---- zero-based ordered-uint float encoding (enc(-inf) == 0) ----
#define ORD_BIAS 0x007FFFFFu
__device__ __forceinline__ unsigned encf(float f) {
    unsigned u = __float_as_uint(f);
    unsigned o = (u & 0x80000000u) ? ~u : (u | 0x80000000u);
    return o - ORD_BIAS;
}
__device__ __forceinline__ float decf(unsigned s) {
    unsigned u = s + ORD_BIAS;
    return __uint_as_float((u & 0x80000000u) ? (u ^ 0x80000000u) : ~u);
}

// ------------------------------------------------------------------
// Kernel 1: pooling — exact R9/R12 configuration (80 regs, ~85us,
// 6.2TB/s, 77% DRAM measured; at practical ceiling). DO NOT PERTURB.
// ------------------------------------------------------------------
__device__ __forceinline__ void flush_seg(int g, float4 a, float4 m, int n, int lane) {
    if ((unsigned)g >= N_GRAPHS) return;
    float*    sp = &g_S.sums[g * HIDDEN + 4 * lane];
    unsigned* mp = &g_S.maxs[g * HIDDEN + 4 * lane];
    atomicAdd(sp + 0, a.x);
    atomicAdd(sp + 1, a.y);
    atomicAdd(sp + 2, a.z);
    atomicAdd(sp + 3, a.w);
    atomicMax(mp + 0, encf(m.x));
    atomicMax(mp + 1, encf(m.y));
    atomicMax(mp + 2, encf(m.z));
    atomicMax(mp + 3, encf(m.w));
    if (lane == 0) atomicAdd(&g_S.counts[g], n);
}

template <typename IT>
__device__ __forceinline__ void pool_span(const float4* __restrict__ x4,
                                          const IT* __restrict__ batch,
                                          int row0, int lane) {
    const float NEG_INF = -__int_as_float(0x7F800000);
    float4 acc = make_float4(0.f, 0.f, 0.f, 0.f);
    float4 mx  = make_float4(NEG_INF, NEG_INF, NEG_INF, NEG_INF);
    int cur = -1, seglen = 0;

    for (int mb = 0; mb < ROWS_PER_WARP / 8; mb++) {
        int base = row0 + mb * 8;
        int    bb[8];
        float4 vv[8];
        #pragma unroll
        for (int i = 0; i < 8; i++) {
            bb[i] = (int)batch[base + i];
            vv[i] = __ldcs(&x4[(size_t)(base + i) * (HIDDEN / 4) + lane]);
        }
        #pragma unroll
        for (int i = 0; i < 8; i++) {
            int g = bb[i];
            if (g != cur) {
                if (cur >= 0) flush_seg(cur, acc, mx, seglen, lane);
                cur = g;
                acc = make_float4(0.f, 0.f, 0.f, 0.f);
                mx  = make_float4(NEG_INF, NEG_INF, NEG_INF, NEG_INF);
                seglen = 0;
            }
            acc.x += vv[i].x; acc.y += vv[i].y; acc.z += vv[i].z; acc.w += vv[i].w;
            mx.x = fmaxf(mx.x, vv[i].x); mx.y = fmaxf(mx.y, vv[i].y);
            mx.z = fmaxf(mx.z, vv[i].z); mx.w = fmaxf(mx.w, vv[i].w);
            seglen++;
        }
    }
    flush_seg(cur, acc, mx, seglen, lane);
}

__global__ __launch_bounds__(POOL_THREADS)
void pool_kernel(const float4* __restrict__ x4, const void* __restrict__ batch) {
    int wg   = (blockIdx.x * blockDim.x + threadIdx.x) >> 5;
    int lane = threadIdx.x & 31;
    if (wg >= N_WARPSPANS) return;
    int row0 = wg * ROWS_PER_WARP;

    // inline dtype probe: sorted ids < 4096 => int64 high words all zero
    const int2* b2 = (const int2*)batch;
    int nz = 0;
    #pragma unroll
    for (int k = 1; k <= 8; k++) {
        nz |= b2[N_NODES / 2 - k].y;
        nz |= b2[N_NODES / 4 + k].y;
    }
    if (nz == 0) pool_span<long long>(x4, (const long long*)batch, row0, lane);
    else         pool_span<int>(x4, (const int*)batch, row0, lane);
}

// ------------------------------------------------------------------
// Kernel 2: split-K GEMM + PDL. N_KT=6 (64-row k-tiles): halves REDG
// partial traffic 25MB -> 12.5MB vs N_KT=12. 34KB smem, (128,6) ->
// 6 blocks/SM, 24 warps/SM. Grid 1536 (~1.7 waves).
// ------------------------------------------------------------------
#define S1_KT   64
#define S1_GPB  16
#define S1_GPW  4
#define N_KT    6

__device__ __forceinline__ void ffma2(unsigned long long& acc,
                                      unsigned long long w2,
                                      unsigned long long p2) {
    asm("fma.rn.f32x2 %0, %1, %2, %0;" : "+l"(acc) : "l"(w2), "l"(p2));
}
__device__ __forceinline__ unsigned long long pack2(float p) {
    unsigned long long r;
    asm("mov.b64 %0, {%1, %1};" : "=l"(r) : "r"(__float_as_uint(p)));
    return r;
}

__global__ __launch_bounds__(128, 6)
void gemm_stage1(const float* __restrict__ W) {
    __shared__ float Ws[S1_KT * HIDDEN];      // 32 KB
    __shared__ float Ps[S1_GPB][S1_KT];       // 4 KB

    int kt   = blockIdx.x / 256;               // 0..5
    int grp  = blockIdx.x % 256;               // 0..255
    int g0   = grp * S1_GPB;
    int tid  = threadIdx.x;                    // 128
    int warp = tid >> 5, lane = tid & 31;
    int glb  = warp * S1_GPW;

    // ---- PDL prologue: W tile (independent of pool) ----
    // 64 rows x 128 cols = 2048 float4 over 128 threads
    const float4* Wg = (const float4*)(W + kt * S1_KT * HIDDEN);
    #pragma unroll
    for (int i = 0; i < 16; i++) ((float4*)Ws)[tid + i * 128] = Wg[tid + i * 128];

    cudaGridDependencySynchronize();

    // Ps: warp's 4 graphs x 64 pooled values. tiles 0-1 mean, 2-3 max, 4-5 sum
    int sec = kt >> 1;
    #pragma unroll
    for (int g = 0; g < S1_GPW; g++) {
        int gg  = g0 + glb + g;
        int cnt = g_S.counts[gg];
        float inv = 1.0f / fmaxf((float)cnt, 1.0f);
        #pragma unroll
        for (int h = 0; h < 2; h++) {
            int j  = h * 32 + lane;                 // 0..63 within tile
            int lc = (kt & 1) * S1_KT + j;          // col within section
            float v;
            if (sec == 0)      v = g_S.sums[gg * HIDDEN + lc] * inv;
            else if (sec == 1) v = (cnt > 0) ? decf(g_S.maxs[gg * HIDDEN + lc]) : 0.f;
            else               v = g_S.sums[gg * HIDDEN + lc];
            Ps[glb + g][j] = v;
        }
    }
    __syncthreads();

    unsigned long long acc[S1_GPW][2];
    #pragma unroll
    for (int g = 0; g < S1_GPW; g++) { acc[g][0] = 0ull; acc[g][1] = 0ull; }

    #pragma unroll 4
    for (int k4 = 0; k4 < S1_KT / 4; k4++) {
        float4 pv[S1_GPW];
        #pragma unroll
        for (int g = 0; g < S1_GPW; g++)
            pv[g] = ((const float4*)Ps[glb + g])[k4];           // broadcast LDS.128
        #pragma unroll
        for (int kk = 0; kk < 4; kk++) {
            ulonglong2 w2 = ((const ulonglong2*)(Ws + (k4 * 4 + kk) * HIDDEN))[lane];
            #pragma unroll
            for (int g = 0; g < S1_GPW; g++) {
                float p = (kk == 0) ? pv[g].x : (kk == 1) ? pv[g].y
                        : (kk == 2) ? pv[g].z : pv[g].w;
                unsigned long long p2 = pack2(p);
                ffma2(acc[g][0], w2.x, p2);
                ffma2(acc[g][1], w2.y, p2);
            }
        }
    }

    // REDG partial accumulation into memset-zeroed g_S.h (6 adds/output)
    #pragma unroll
    for (int g = 0; g < S1_GPW; g++) {
        int gg = g0 + glb + g;
        float* hp = &g_S.h[gg * HIDDEN + 4 * lane];
        unsigned lo, hi;
        asm("mov.b64 {%0, %1}, %2;" : "=r"(lo), "=r"(hi) : "l"(acc[g][0]));
        atomicAdd(hp + 0, __uint_as_float(lo));
        atomicAdd(hp + 1, __uint_as_float(hi));
        asm("mov.b64 {%0, %1}, %2;" : "=r"(lo), "=r"(hi) : "l"(acc[g][1]));
        atomicAdd(hp + 2, __uint_as_float(lo));
        atomicAdd(hp + 3, __uint_as_float(hi));
    }
}

// ------------------------------------------------------------------
// Kernel 3: finisher + PDL — bias + LayerNorm + exact GELU.
// 512 blocks x 256 threads (R12 measured config).
// ------------------------------------------------------------------
__global__ __launch_bounds__(256)
void finish_kernel(const float* __restrict__ bias, const float* __restrict__ gamma,
                   const float* __restrict__ beta, float* __restrict__ out) {
    int tid  = threadIdx.x;
    int warp = tid >> 5, lane = tid & 31;
    int g    = blockIdx.x * 8 + warp;

    // ---- PDL prologue: params (independent of gemm) ----
    float4 b4 = ((const float4*)bias)[lane];
    float4 gm = ((const float4*)gamma)[lane];
    float4 bt = ((const float4*)beta)[lane];

    cudaGridDependencySynchronize();

    float4 p = ((const float4*)g_S.h)[(size_t)g * (HIDDEN / 4) + lane];
    float h[4];
    h[0] = p.x + b4.x; h[1] = p.y + b4.y; h[2] = p.z + b4.z; h[3] = p.w + b4.w;

    float s = h[0] + h[1] + h[2] + h[3];
    #pragma unroll
    for (int o = 16; o; o >>= 1) s += __shfl_xor_sync(0xFFFFFFFFu, s, o);
    float mu = s * (1.0f / 128.0f);

    float d0 = h[0]-mu, d1 = h[1]-mu, d2 = h[2]-mu, d3 = h[3]-mu;
    float v = d0*d0 + d1*d1 + d2*d2 + d3*d3;
    #pragma unroll
    for (int o = 16; o; o >>= 1) v += __shfl_xor_sync(0xFFFFFFFFu, v, o);
    float rstd = rsqrtf(v * (1.0f / 128.0f) + 1e-5f);

    float gmv[4] = {gm.x, gm.y, gm.z, gm.w};
    float btv[4] = {bt.x, bt.y, bt.z, bt.w};
    float4 o4;
    float* ov = (float*)&o4;
    #pragma unroll
    for (int k = 0; k < 4; k++) {
        float t = (h[k] - mu) * rstd * gmv[k] + btv[k];
        ov[k] = 0.5f * t * (1.0f + erff(t * 0.70710678118654752f));
    }
    ((float4*)out)[(size_t)g * (HIDDEN / 4) + lane] = o4;
}

// ------------------------------------------------------------------
extern "C" void kernel_launch(void* const* d_in, const int* in_sizes, int n_in,
                              void* d_out, int out_size) {
    const float* x     = nullptr;
    const void*  batch = nullptr;
    const float* W     = nullptr;
    const float* b     = nullptr;
    const float* gamma = nullptr;
    const float* beta  = nullptr;

    for (int i = 0; i < n_in; i++) {
        int s = in_sizes[i];
        if (s == N_NODES * HIDDEN)         x = (const float*)d_in[i];
        else if (s == N_NODES)             batch = d_in[i];
        else if (s == 3 * HIDDEN * HIDDEN) W = (const float*)d_in[i];
        else if (s == HIDDEN) {
            if (!b) b = (const float*)d_in[i];
            else if (!gamma) gamma = (const float*)d_in[i];
            else if (!beta)  beta = (const float*)d_in[i];
        }
    }

    // single memset node replaces the init kernel (zero-based max encoding)
    void* scratch_ptr = nullptr;
    cudaGetSymbolAddress(&scratch_ptr, g_S);
    cudaMemsetAsync(scratch_ptr, 0, sizeof(Scratch), 0);

    // pool: plain launch (fastest measured pool — do not perturb)
    pool_kernel<<<POOL_BLOCKS, POOL_THREADS>>>((const float4*)x, batch);

    // PDL on the two tail kernels (prologue overlap)
    cudaLaunchAttribute pdl[1];
    pdl[0].id = cudaLaunchAttributeProgrammaticStreamSerialization;
    pdl[0].val.programmaticStreamSerializationAllowed = 1;

    {
        cudaLaunchConfig_t cfg = {};
        cfg.gridDim  = dim3(N_KT * 256);
        cfg.blockDim = dim3(128);
        cfg.stream   = 0;
        cfg.attrs    = pdl;
        cfg.numAttrs = 1;
        cudaLaunchKernelEx(&cfg, gemm_stage1, W);
    }
    {
        cudaLaunchConfig_t cfg = {};
        cfg.gridDim  = dim3(N_GRAPHS / 8);
        cfg.blockDim = dim3(256);
        cfg.stream   = 0;
        cfg.attrs    = pdl;
        cfg.numAttrs = 1;
        cudaLaunchKernelEx(&cfg, finish_kernel, b, gamma, beta, (float*)d_out);
    }
}

// round 16
// speedup vs baseline: 1.1003x; 1.0051x over previous
#include <cuda_runtime.h>
#include <cuda_bf16.h>
#include <cstdint>

// Problem constants (fixed-shape problem)
#define HIDDEN   128
#define N_NODES  1000000
#define N_GRAPHS 4096

#define ROWS_PER_WARP 64
#define N_WARPSPANS   (N_NODES / ROWS_PER_WARP)   // 15625
#define POOL_THREADS  256
#define POOL_BLOCKS   ((N_WARPSPANS + (POOL_THREADS/32) - 1) / (POOL_THREADS/32))

#define N_KT    6

// ------------------------------------------------------------------
// Scratch. Memset covers ONLY sums/maxs/counts (4.2MB). g_hpart needs
// no init: every slot is written by gemm before finish reads it.
// maxs=0 == enc(-inf) via zero-based encoding.
// ------------------------------------------------------------------
struct Scratch {
    float    sums[N_GRAPHS * HIDDEN];
    unsigned maxs[N_GRAPHS * HIDDEN];
    int      counts[N_GRAPHS];
};
__device__ __align__(16) Scratch g_S;
__device__ __align__(16) float g_hpart[N_KT * N_GRAPHS * HIDDEN];   // 12.6MB, no init

// ---- zero-based ordered-uint float encoding (enc(-inf) == 0) ----
#define ORD_BIAS 0x007FFFFFu
__device__ __forceinline__ unsigned encf(float f) {
    unsigned u = __float_as_uint(f);
    unsigned o = (u & 0x80000000u) ? ~u : (u | 0x80000000u);
    return o - ORD_BIAS;
}
__device__ __forceinline__ float decf(unsigned s) {
    unsigned u = s + ORD_BIAS;
    return __uint_as_float((u & 0x80000000u) ? (u ^ 0x80000000u) : ~u);
}

// ------------------------------------------------------------------
// Kernel 1: pooling — exact R9/R12/R15 configuration (80 regs, ~85us,
// 6.2TB/s measured; at practical ceiling). DO NOT PERTURB.
// ------------------------------------------------------------------
__device__ __forceinline__ void flush_seg(int g, float4 a, float4 m, int n, int lane) {
    if ((unsigned)g >= N_GRAPHS) return;
    float*    sp = &g_S.sums[g * HIDDEN + 4 * lane];
    unsigned* mp = &g_S.maxs[g * HIDDEN + 4 * lane];
    atomicAdd(sp + 0, a.x);
    atomicAdd(sp + 1, a.y);
    atomicAdd(sp + 2, a.z);
    atomicAdd(sp + 3, a.w);
    atomicMax(mp + 0, encf(m.x));
    atomicMax(mp + 1, encf(m.y));
    atomicMax(mp + 2, encf(m.z));
    atomicMax(mp + 3, encf(m.w));
    if (lane == 0) atomicAdd(&g_S.counts[g], n);
}

template <typename IT>
__device__ __forceinline__ void pool_span(const float4* __restrict__ x4,
                                          const IT* __restrict__ batch,
                                          int row0, int lane) {
    const float NEG_INF = -__int_as_float(0x7F800000);
    float4 acc = make_float4(0.f, 0.f, 0.f, 0.f);
    float4 mx  = make_float4(NEG_INF, NEG_INF, NEG_INF, NEG_INF);
    int cur = -1, seglen = 0;

    for (int mb = 0; mb < ROWS_PER_WARP / 8; mb++) {
        int base = row0 + mb * 8;
        int    bb[8];
        float4 vv[8];
        #pragma unroll
        for (int i = 0; i < 8; i++) {
            bb[i] = (int)batch[base + i];
            vv[i] = __ldcs(&x4[(size_t)(base + i) * (HIDDEN / 4) + lane]);
        }
        #pragma unroll
        for (int i = 0; i < 8; i++) {
            int g = bb[i];
            if (g != cur) {
                if (cur >= 0) flush_seg(cur, acc, mx, seglen, lane);
                cur = g;
                acc = make_float4(0.f, 0.f, 0.f, 0.f);
                mx  = make_float4(NEG_INF, NEG_INF, NEG_INF, NEG_INF);
                seglen = 0;
            }
            acc.x += vv[i].x; acc.y += vv[i].y; acc.z += vv[i].z; acc.w += vv[i].w;
            mx.x = fmaxf(mx.x, vv[i].x); mx.y = fmaxf(mx.y, vv[i].y);
            mx.z = fmaxf(mx.z, vv[i].z); mx.w = fmaxf(mx.w, vv[i].w);
            seglen++;
        }
    }
    flush_seg(cur, acc, mx, seglen, lane);
}

__global__ __launch_bounds__(POOL_THREADS)
void pool_kernel(const float4* __restrict__ x4, const void* __restrict__ batch) {
    int wg   = (blockIdx.x * blockDim.x + threadIdx.x) >> 5;
    int lane = threadIdx.x & 31;
    if (wg >= N_WARPSPANS) return;
    int row0 = wg * ROWS_PER_WARP;

    // inline dtype probe: sorted ids < 4096 => int64 high words all zero
    const int2* b2 = (const int2*)batch;
    int nz = 0;
    #pragma unroll
    for (int k = 1; k <= 8; k++) {
        nz |= b2[N_NODES / 2 - k].y;
        nz |= b2[N_NODES / 4 + k].y;
    }
    if (nz == 0) pool_span<long long>(x4, (const long long*)batch, row0, lane);
    else         pool_span<int>(x4, (const int*)batch, row0, lane);
}

// ------------------------------------------------------------------
// Kernel 2: split-K GEMM + PDL. N_KT=6 (64-row k-tiles). Partials are
// DIRECT STORES (STG.128 coalesced) into g_hpart — zero atomics.
// 36KB smem, (128,6) -> 6 blocks/SM, 24 warps/SM. Grid 1536.
// ------------------------------------------------------------------
#define S1_KT   64
#define S1_GPB  16
#define S1_GPW  4

__device__ __forceinline__ void ffma2(unsigned long long& acc,
                                      unsigned long long w2,
                                      unsigned long long p2) {
    asm("fma.rn.f32x2 %0, %1, %2, %0;" : "+l"(acc) : "l"(w2), "l"(p2));
}
__device__ __forceinline__ unsigned long long pack2(float p) {
    unsigned long long r;
    asm("mov.b64 %0, {%1, %1};" : "=l"(r) : "r"(__float_as_uint(p)));
    return r;
}

__global__ __launch_bounds__(128, 6)
void gemm_stage1(const float* __restrict__ W) {
    __shared__ float Ws[S1_KT * HIDDEN];      // 32 KB
    __shared__ float Ps[S1_GPB][S1_KT];       // 4 KB

    int kt   = blockIdx.x / 256;               // 0..5
    int grp  = blockIdx.x % 256;               // 0..255
    int g0   = grp * S1_GPB;
    int tid  = threadIdx.x;                    // 128
    int warp = tid >> 5, lane = tid & 31;
    int glb  = warp * S1_GPW;

    // ---- PDL prologue: W tile (independent of pool) ----
    const float4* Wg = (const float4*)(W + kt * S1_KT * HIDDEN);
    #pragma unroll
    for (int i = 0; i < 16; i++) ((float4*)Ws)[tid + i * 128] = Wg[tid + i * 128];

    cudaGridDependencySynchronize();

    // Ps: warp's 4 graphs x 64 pooled values. tiles 0-1 mean, 2-3 max, 4-5 sum
    int sec = kt >> 1;
    #pragma unroll
    for (int g = 0; g < S1_GPW; g++) {
        int gg  = g0 + glb + g;
        int cnt = g_S.counts[gg];
        float inv = 1.0f / fmaxf((float)cnt, 1.0f);
        #pragma unroll
        for (int h = 0; h < 2; h++) {
            int j  = h * 32 + lane;                 // 0..63 within tile
            int lc = (kt & 1) * S1_KT + j;          // col within section
            float v;
            if (sec == 0)      v = g_S.sums[gg * HIDDEN + lc] * inv;
            else if (sec == 1) v = (cnt > 0) ? decf(g_S.maxs[gg * HIDDEN + lc]) : 0.f;
            else               v = g_S.sums[gg * HIDDEN + lc];
            Ps[glb + g][j] = v;
        }
    }
    __syncthreads();

    unsigned long long acc[S1_GPW][2];
    #pragma unroll
    for (int g = 0; g < S1_GPW; g++) { acc[g][0] = 0ull; acc[g][1] = 0ull; }

    #pragma unroll 4
    for (int k4 = 0; k4 < S1_KT / 4; k4++) {
        float4 pv[S1_GPW];
        #pragma unroll
        for (int g = 0; g < S1_GPW; g++)
            pv[g] = ((const float4*)Ps[glb + g])[k4];           // broadcast LDS.128
        #pragma unroll
        for (int kk = 0; kk < 4; kk++) {
            ulonglong2 w2 = ((const ulonglong2*)(Ws + (k4 * 4 + kk) * HIDDEN))[lane];
            #pragma unroll
            for (int g = 0; g < S1_GPW; g++) {
                float p = (kk == 0) ? pv[g].x : (kk == 1) ? pv[g].y
                        : (kk == 2) ? pv[g].z : pv[g].w;
                unsigned long long p2 = pack2(p);
                ffma2(acc[g][0], w2.x, p2);
                ffma2(acc[g][1], w2.y, p2);
            }
        }
    }

    // direct-store partials (coalesced STG.128, zero atomics)
    #pragma unroll
    for (int g = 0; g < S1_GPW; g++) {
        int gg = g0 + glb + g;
        float4 o;
        unsigned lo, hi;
        asm("mov.b64 {%0, %1}, %2;" : "=r"(lo), "=r"(hi) : "l"(acc[g][0]));
        o.x = __uint_as_float(lo); o.y = __uint_as_float(hi);
        asm("mov.b64 {%0, %1}, %2;" : "=r"(lo), "=r"(hi) : "l"(acc[g][1]));
        o.z = __uint_as_float(lo); o.w = __uint_as_float(hi);
        ((float4*)g_hpart)[((size_t)kt * N_GRAPHS + gg) * (HIDDEN / 4) + lane] = o;
    }
}

// ------------------------------------------------------------------
// Kernel 3: finisher + PDL — reduce 6 partials + bias + LN + GELU.
// 512 blocks x 256 threads; warp = 1 graph; 6 independent LDG.128.
// ------------------------------------------------------------------
__global__ __launch_bounds__(256)
void finish_kernel(const float* __restrict__ bias, const float* __restrict__ gamma,
                   const float* __restrict__ beta, float* __restrict__ out) {
    int tid  = threadIdx.x;
    int warp = tid >> 5, lane = tid & 31;
    int g    = blockIdx.x * 8 + warp;

    // ---- PDL prologue: params (independent of gemm) ----
    float4 b4 = ((const float4*)bias)[lane];
    float4 gm = ((const float4*)gamma)[lane];
    float4 bt = ((const float4*)beta)[lane];

    cudaGridDependencySynchronize();

    float4 pp[N_KT];
    #pragma unroll
    for (int kt = 0; kt < N_KT; kt++)
        pp[kt] = ((const float4*)g_hpart)[((size_t)kt * N_GRAPHS + g) * (HIDDEN / 4) + lane];

    float h[4];
    h[0] = b4.x; h[1] = b4.y; h[2] = b4.z; h[3] = b4.w;
    #pragma unroll
    for (int kt = 0; kt < N_KT; kt++) {
        h[0] += pp[kt].x; h[1] += pp[kt].y; h[2] += pp[kt].z; h[3] += pp[kt].w;
    }

    float s = h[0] + h[1] + h[2] + h[3];
    #pragma unroll
    for (int o = 16; o; o >>= 1) s += __shfl_xor_sync(0xFFFFFFFFu, s, o);
    float mu = s * (1.0f / 128.0f);

    float d0 = h[0]-mu, d1 = h[1]-mu, d2 = h[2]-mu, d3 = h[3]-mu;
    float v = d0*d0 + d1*d1 + d2*d2 + d3*d3;
    #pragma unroll
    for (int o = 16; o; o >>= 1) v += __shfl_xor_sync(0xFFFFFFFFu, v, o);
    float rstd = rsqrtf(v * (1.0f / 128.0f) + 1e-5f);

    float gmv[4] = {gm.x, gm.y, gm.z, gm.w};
    float btv[4] = {bt.x, bt.y, bt.z, bt.w};
    float4 o4;
    float* ov = (float*)&o4;
    #pragma unroll
    for (int k = 0; k < 4; k++) {
        float t = (h[k] - mu) * rstd * gmv[k] + btv[k];
        ov[k] = 0.5f * t * (1.0f + erff(t * 0.70710678118654752f));
    }
    ((float4*)out)[(size_t)g * (HIDDEN / 4) + lane] = o4;
}

// ------------------------------------------------------------------
extern "C" void kernel_launch(void* const* d_in, const int* in_sizes, int n_in,
                              void* d_out, int out_size) {
    const float* x     = nullptr;
    const void*  batch = nullptr;
    const float* W     = nullptr;
    const float* b     = nullptr;
    const float* gamma = nullptr;
    const float* beta  = nullptr;

    for (int i = 0; i < n_in; i++) {
        int s = in_sizes[i];
        if (s == N_NODES * HIDDEN)         x = (const float*)d_in[i];
        else if (s == N_NODES)             batch = d_in[i];
        else if (s == 3 * HIDDEN * HIDDEN) W = (const float*)d_in[i];
        else if (s == HIDDEN) {
            if (!b) b = (const float*)d_in[i];
            else if (!gamma) gamma = (const float*)d_in[i];
            else if (!beta)  beta = (const float*)d_in[i];
        }
    }

    // memset now only 4.2MB (sums+maxs+counts); g_hpart needs no init
    void* scratch_ptr = nullptr;
    cudaGetSymbolAddress(&scratch_ptr, g_S);
    cudaMemsetAsync(scratch_ptr, 0, sizeof(Scratch), 0);

    // pool: plain launch (fastest measured pool — do not perturb)
    pool_kernel<<<POOL_BLOCKS, POOL_THREADS>>>((const float4*)x, batch);

    // PDL on the two tail kernels (prologue overlap)
    cudaLaunchAttribute pdl[1];
    pdl[0].id = cudaLaunchAttributeProgrammaticStreamSerialization;
    pdl[0].val.programmaticStreamSerializationAllowed = 1;

    {
        cudaLaunchConfig_t cfg = {};
        cfg.gridDim  = dim3(N_KT * 256);
        cfg.blockDim = dim3(128);
        cfg.stream   = 0;
        cfg.attrs    = pdl;
        cfg.numAttrs = 1;
        cudaLaunchKernelEx(&cfg, gemm_stage1, W);
    }
    {
        cudaLaunchConfig_t cfg = {};
        cfg.gridDim  = dim3(N_GRAPHS / 8);
        cfg.blockDim = dim3(256);
        cfg.stream   = 0;
        cfg.attrs    = pdl;
        cfg.numAttrs = 1;
        cudaLaunchKernelEx(&cfg, finish_kernel, b, gamma, beta, (float*)d_out);
    }
}

// round 17
// speedup vs baseline: 1.1219x; 1.0196x over previous
#include <cuda_runtime.h>
#include <cuda_bf16.h>
#include <cstdint>

// Problem constants (fixed-shape problem)
#define HIDDEN   128
#define N_NODES  1000000
#define N_GRAPHS 4096

#define ROWS_PER_WARP 64
#define N_WARPSPANS   (N_NODES / ROWS_PER_WARP)   // 15625
#define POOL_THREADS  256
#define POOL_BLOCKS   ((N_WARPSPANS + (POOL_THREADS/32) - 1) / (POOL_THREADS/32))

#define N_KT    6

// ------------------------------------------------------------------
// Scratch. NO memset node: __device__ globals are zero-initialized at
// module load (first call), and finish_kernel re-zeroes g_S at the end
// of EVERY call for the next replay (it no longer reads g_S itself).
// g_hpart needs no init: every slot is written by gemm before finish
// reads it. maxs=0 == enc(-inf) via zero-based encoding.
// ------------------------------------------------------------------
struct Scratch {
    float    sums[N_GRAPHS * HIDDEN];
    unsigned maxs[N_GRAPHS * HIDDEN];
    int      counts[N_GRAPHS];
};
__device__ __align__(16) Scratch g_S;
__device__ __align__(16) float g_hpart[N_KT * N_GRAPHS * HIDDEN];   // 12.6MB, no init

#define SCRATCH_F4 ((int)(sizeof(Scratch) / 16))   // 263168 float4s

// ---- zero-based ordered-uint float encoding (enc(-inf) == 0) ----
#define ORD_BIAS 0x007FFFFFu
__device__ __forceinline__ unsigned encf(float f) {
    unsigned u = __float_as_uint(f);
    unsigned o = (u & 0x80000000u) ? ~u : (u | 0x80000000u);
    return o - ORD_BIAS;
}
__device__ __forceinline__ float decf(unsigned s) {
    unsigned u = s + ORD_BIAS;
    return __uint_as_float((u & 0x80000000u) ? (u ^ 0x80000000u) : ~u);
}

// ------------------------------------------------------------------
// Kernel 1: pooling — exact R9/R12/R15/R16 configuration (80 regs,
// ~85us, 6.2TB/s measured; at practical ceiling). DO NOT PERTURB.
// ------------------------------------------------------------------
__device__ __forceinline__ void flush_seg(int g, float4 a, float4 m, int n, int lane) {
    if ((unsigned)g >= N_GRAPHS) return;
    float*    sp = &g_S.sums[g * HIDDEN + 4 * lane];
    unsigned* mp = &g_S.maxs[g * HIDDEN + 4 * lane];
    atomicAdd(sp + 0, a.x);
    atomicAdd(sp + 1, a.y);
    atomicAdd(sp + 2, a.z);
    atomicAdd(sp + 3, a.w);
    atomicMax(mp + 0, encf(m.x));
    atomicMax(mp + 1, encf(m.y));
    atomicMax(mp + 2, encf(m.z));
    atomicMax(mp + 3, encf(m.w));
    if (lane == 0) atomicAdd(&g_S.counts[g], n);
}

template <typename IT>
__device__ __forceinline__ void pool_span(const float4* __restrict__ x4,
                                          const IT* __restrict__ batch,
                                          int row0, int lane) {
    const float NEG_INF = -__int_as_float(0x7F800000);
    float4 acc = make_float4(0.f, 0.f, 0.f, 0.f);
    float4 mx  = make_float4(NEG_INF, NEG_INF, NEG_INF, NEG_INF);
    int cur = -1, seglen = 0;

    for (int mb = 0; mb < ROWS_PER_WARP / 8; mb++) {
        int base = row0 + mb * 8;
        int    bb[8];
        float4 vv[8];
        #pragma unroll
        for (int i = 0; i < 8; i++) {
            bb[i] = (int)batch[base + i];
            vv[i] = __ldcs(&x4[(size_t)(base + i) * (HIDDEN / 4) + lane]);
        }
        #pragma unroll
        for (int i = 0; i < 8; i++) {
            int g = bb[i];
            if (g != cur) {
                if (cur >= 0) flush_seg(cur, acc, mx, seglen, lane);
                cur = g;
                acc = make_float4(0.f, 0.f, 0.f, 0.f);
                mx  = make_float4(NEG_INF, NEG_INF, NEG_INF, NEG_INF);
                seglen = 0;
            }
            acc.x += vv[i].x; acc.y += vv[i].y; acc.z += vv[i].z; acc.w += vv[i].w;
            mx.x = fmaxf(mx.x, vv[i].x); mx.y = fmaxf(mx.y, vv[i].y);
            mx.z = fmaxf(mx.z, vv[i].z); mx.w = fmaxf(mx.w, vv[i].w);
            seglen++;
        }
    }
    flush_seg(cur, acc, mx, seglen, lane);
}

__global__ __launch_bounds__(POOL_THREADS)
void pool_kernel(const float4* __restrict__ x4, const void* __restrict__ batch) {
    int wg   = (blockIdx.x * blockDim.x + threadIdx.x) >> 5;
    int lane = threadIdx.x & 31;
    if (wg >= N_WARPSPANS) return;
    int row0 = wg * ROWS_PER_WARP;

    // inline dtype probe: sorted ids < 4096 => int64 high words all zero
    const int2* b2 = (const int2*)batch;
    int nz = 0;
    #pragma unroll
    for (int k = 1; k <= 8; k++) {
        nz |= b2[N_NODES / 2 - k].y;
        nz |= b2[N_NODES / 4 + k].y;
    }
    if (nz == 0) pool_span<long long>(x4, (const long long*)batch, row0, lane);
    else         pool_span<int>(x4, (const int*)batch, row0, lane);
}

// ------------------------------------------------------------------
// Kernel 2: split-K GEMM + PDL. N_KT=6 (64-row k-tiles). Partials are
// DIRECT STORES (STG.128 coalesced) into g_hpart — zero atomics.
// 36KB smem, (128,6) -> 6 blocks/SM, 24 warps/SM. Grid 1536.
// ------------------------------------------------------------------
#define S1_KT   64
#define S1_GPB  16
#define S1_GPW  4

__device__ __forceinline__ void ffma2(unsigned long long& acc,
                                      unsigned long long w2,
                                      unsigned long long p2) {
    asm("fma.rn.f32x2 %0, %1, %2, %0;" : "+l"(acc) : "l"(w2), "l"(p2));
}
__device__ __forceinline__ unsigned long long pack2(float p) {
    unsigned long long r;
    asm("mov.b64 %0, {%1, %1};" : "=l"(r) : "r"(__float_as_uint(p)));
    return r;
}

__global__ __launch_bounds__(128, 6)
void gemm_stage1(const float* __restrict__ W) {
    __shared__ float Ws[S1_KT * HIDDEN];      // 32 KB
    __shared__ float Ps[S1_GPB][S1_KT];       // 4 KB

    int kt   = blockIdx.x / 256;               // 0..5
    int grp  = blockIdx.x % 256;               // 0..255
    int g0   = grp * S1_GPB;
    int tid  = threadIdx.x;                    // 128
    int warp = tid >> 5, lane = tid & 31;
    int glb  = warp * S1_GPW;

    // ---- PDL prologue: W tile (independent of pool) ----
    const float4* Wg = (const float4*)(W + kt * S1_KT * HIDDEN);
    #pragma unroll
    for (int i = 0; i < 16; i++) ((float4*)Ws)[tid + i * 128] = Wg[tid + i * 128];

    cudaGridDependencySynchronize();

    // Ps: warp's 4 graphs x 64 pooled values. tiles 0-1 mean, 2-3 max, 4-5 sum
    int sec = kt >> 1;
    #pragma unroll
    for (int g = 0; g < S1_GPW; g++) {
        int gg  = g0 + glb + g;
        int cnt = g_S.counts[gg];
        float inv = 1.0f / fmaxf((float)cnt, 1.0f);
        #pragma unroll
        for (int h = 0; h < 2; h++) {
            int j  = h * 32 + lane;                 // 0..63 within tile
            int lc = (kt & 1) * S1_KT + j;          // col within section
            float v;
            if (sec == 0)      v = g_S.sums[gg * HIDDEN + lc] * inv;
            else if (sec == 1) v = (cnt > 0) ? decf(g_S.maxs[gg * HIDDEN + lc]) : 0.f;
            else               v = g_S.sums[gg * HIDDEN + lc];
            Ps[glb + g][j] = v;
        }
    }
    __syncthreads();

    unsigned long long acc[S1_GPW][2];
    #pragma unroll
    for (int g = 0; g < S1_GPW; g++) { acc[g][0] = 0ull; acc[g][1] = 0ull; }

    #pragma unroll 4
    for (int k4 = 0; k4 < S1_KT / 4; k4++) {
        float4 pv[S1_GPW];
        #pragma unroll
        for (int g = 0; g < S1_GPW; g++)
            pv[g] = ((const float4*)Ps[glb + g])[k4];           // broadcast LDS.128
        #pragma unroll
        for (int kk = 0; kk < 4; kk++) {
            ulonglong2 w2 = ((const ulonglong2*)(Ws + (k4 * 4 + kk) * HIDDEN))[lane];
            #pragma unroll
            for (int g = 0; g < S1_GPW; g++) {
                float p = (kk == 0) ? pv[g].x : (kk == 1) ? pv[g].y
                        : (kk == 2) ? pv[g].z : pv[g].w;
                unsigned long long p2 = pack2(p);
                ffma2(acc[g][0], w2.x, p2);
                ffma2(acc[g][1], w2.y, p2);
            }
        }
    }

    // direct-store partials (coalesced STG.128, zero atomics)
    #pragma unroll
    for (int g = 0; g < S1_GPW; g++) {
        int gg = g0 + glb + g;
        float4 o;
        unsigned lo, hi;
        asm("mov.b64 {%0, %1}, %2;" : "=r"(lo), "=r"(hi) : "l"(acc[g][0]));
        o.x = __uint_as_float(lo); o.y = __uint_as_float(hi);
        asm("mov.b64 {%0, %1}, %2;" : "=r"(lo), "=r"(hi) : "l"(acc[g][1]));
        o.z = __uint_as_float(lo); o.w = __uint_as_float(hi);
        ((float4*)g_hpart)[((size_t)kt * N_GRAPHS + gg) * (HIDDEN / 4) + lane] = o;
    }
}

// ------------------------------------------------------------------
// Kernel 3: finisher + PDL — reduce 6 partials + bias + LN + GELU,
// then zero g_S for the NEXT replay (finish no longer reads g_S, and
// gemm — which does — has already completed via the PDL dependency).
// 512 blocks x 256 threads; warp = 1 graph.
// ------------------------------------------------------------------
__global__ __launch_bounds__(256)
void finish_kernel(const float* __restrict__ bias, const float* __restrict__ gamma,
                   const float* __restrict__ beta, float* __restrict__ out) {
    int tid  = threadIdx.x;
    int warp = tid >> 5, lane = tid & 31;
    int g    = blockIdx.x * 8 + warp;

    // ---- PDL prologue: params (independent of gemm) ----
    float4 b4 = ((const float4*)bias)[lane];
    float4 gm = ((const float4*)gamma)[lane];
    float4 bt = ((const float4*)beta)[lane];

    cudaGridDependencySynchronize();

    float4 pp[N_KT];
    #pragma unroll
    for (int kt = 0; kt < N_KT; kt++)
        pp[kt] = ((const float4*)g_hpart)[((size_t)kt * N_GRAPHS + g) * (HIDDEN / 4) + lane];

    float h[4];
    h[0] = b4.x; h[1] = b4.y; h[2] = b4.z; h[3] = b4.w;
    #pragma unroll
    for (int kt = 0; kt < N_KT; kt++) {
        h[0] += pp[kt].x; h[1] += pp[kt].y; h[2] += pp[kt].z; h[3] += pp[kt].w;
    }

    float s = h[0] + h[1] + h[2] + h[3];
    #pragma unroll
    for (int o = 16; o; o >>= 1) s += __shfl_xor_sync(0xFFFFFFFFu, s, o);
    float mu = s * (1.0f / 128.0f);

    float d0 = h[0]-mu, d1 = h[1]-mu, d2 = h[2]-mu, d3 = h[3]-mu;
    float v = d0*d0 + d1*d1 + d2*d2 + d3*d3;
    #pragma unroll
    for (int o = 16; o; o >>= 1) v += __shfl_xor_sync(0xFFFFFFFFu, v, o);
    float rstd = rsqrtf(v * (1.0f / 128.0f) + 1e-5f);

    float gmv[4] = {gm.x, gm.y, gm.z, gm.w};
    float btv[4] = {bt.x, bt.y, bt.z, bt.w};
    float4 o4;
    float* ov = (float*)&o4;
    #pragma unroll
    for (int k = 0; k < 4; k++) {
        float t = (h[k] - mu) * rstd * gmv[k] + btv[k];
        ov[k] = 0.5f * t * (1.0f + erff(t * 0.70710678118654752f));
    }
    ((float4*)out)[(size_t)g * (HIDDEN / 4) + lane] = o4;

    // ---- zero g_S for the next replay (replaces the memset node) ----
    {
        float4* sc = (float4*)&g_S;
        float4  z4 = make_float4(0.f, 0.f, 0.f, 0.f);
        int idx = blockIdx.x * 256 + tid;                  // 0..131071
        #pragma unroll
        for (int i = 0; i < 3; i++) {                      // covers 263168 f4s
            int j = idx + i * 131072;
            if (j < SCRATCH_F4) sc[j] = z4;
        }
    }
}

// ------------------------------------------------------------------
extern "C" void kernel_launch(void* const* d_in, const int* in_sizes, int n_in,
                              void* d_out, int out_size) {
    const float* x     = nullptr;
    const void*  batch = nullptr;
    const float* W     = nullptr;
    const float* b     = nullptr;
    const float* gamma = nullptr;
    const float* beta  = nullptr;

    for (int i = 0; i < n_in; i++) {
        int s = in_sizes[i];
        if (s == N_NODES * HIDDEN)         x = (const float*)d_in[i];
        else if (s == N_NODES)             batch = d_in[i];
        else if (s == 3 * HIDDEN * HIDDEN) W = (const float*)d_in[i];
        else if (s == HIDDEN) {
            if (!b) b = (const float*)d_in[i];
            else if (!gamma) gamma = (const float*)d_in[i];
            else if (!beta)  beta = (const float*)d_in[i];
        }
    }

    // NO memset: first call uses load-time zero-init of g_S; every call
    // leaves g_S zeroed for the next (finish_kernel tail).

    // pool: plain launch (fastest measured pool — do not perturb)
    pool_kernel<<<POOL_BLOCKS, POOL_THREADS>>>((const float4*)x, batch);

    // PDL on the two tail kernels (prologue overlap)
    cudaLaunchAttribute pdl[1];
    pdl[0].id = cudaLaunchAttributeProgrammaticStreamSerialization;
    pdl[0].val.programmaticStreamSerializationAllowed = 1;

    {
        cudaLaunchConfig_t cfg = {};
        cfg.gridDim  = dim3(N_KT * 256);
        cfg.blockDim = dim3(128);
        cfg.stream   = 0;
        cfg.attrs    = pdl;
        cfg.numAttrs = 1;
        cudaLaunchKernelEx(&cfg, gemm_stage1, W);
    }
    {
        cudaLaunchConfig_t cfg = {};
        cfg.gridDim  = dim3(N_GRAPHS / 8);
        cfg.blockDim = dim3(256);
        cfg.stream   = 0;
        cfg.attrs    = pdl;
        cfg.numAttrs = 1;
        cudaLaunchKernelEx(&cfg, finish_kernel, b, gamma, beta, (float*)d_out);
    }
}